// round 10
// baseline (speedup 1.0000x reference)
#include <cuda_runtime.h>
#include <math.h>

// x: (2,8,512,256,8), prev_qk: (2,8,8,512,512), conv w: (8,8,3,3), w*: (8,256,256)
// out = out(2,8,512,256,8) ++ qk(2,8,8,512,512)
#define QK_OFF 16777216ull

// ---------------- scratch (tf32 bit patterns stored as float) ----------------
__device__ float g_conv[3u * 1024u * 8u * 256u * 8u];   // [qkv][n][c][h][w] (tf32)
__device__ float g_q[128u * 512u * 256u];               // [head][l][d] (tf32)
__device__ float g_k[128u * 512u * 256u];
__device__ float g_v[128u * 512u * 256u];
__device__ float g_p[128u * 512u * 512u];               // normalized probs (tf32)
__device__ float g_a[16u * 512u * 2048u];               // [bc][l][h][w] (tf32)
__device__ float g_wt[4u * 8u * 256u * 256u];           // weights (tf32): wq,wk,wv,wo

// ---------------- helpers ----------------
__device__ __forceinline__ unsigned f2tf(float x) {
    unsigned u;
    asm("cvt.rna.tf32.f32 %0, %1;" : "=r"(u) : "f"(x));
    return u;
}
__device__ __forceinline__ float tfbits(float x) { return __uint_as_float(f2tf(x)); }
__device__ __forceinline__ void mma8(float c[4], const unsigned a[4], const unsigned b[2]) {
    asm volatile(
        "mma.sync.aligned.m16n8k8.row.col.f32.tf32.tf32.f32 "
        "{%0,%1,%2,%3},{%4,%5,%6,%7},{%8,%9},{%0,%1,%2,%3};"
        : "+f"(c[0]), "+f"(c[1]), "+f"(c[2]), "+f"(c[3])
        : "r"(a[0]), "r"(a[1]), "r"(a[2]), "r"(a[3]), "r"(b[0]), "r"(b[1]));
}
__device__ __forceinline__ float ex2(float x) {
    float r;
    asm("ex2.approx.f32 %0, %1;" : "=f"(r) : "f"(x));
    return r;
}
__device__ __forceinline__ void cp16(void* dst, const void* src) {
    unsigned d = (unsigned)__cvta_generic_to_shared(dst);
    asm volatile("cp.async.cg.shared.global [%0], [%1], 16;" :: "r"(d), "l"(src));
}
#define CP_COMMIT asm volatile("cp.async.commit_group;")
#define CP_WAIT1 asm volatile("cp.async.wait_group 1;")
#define CP_WAIT0 asm volatile("cp.async.wait_group 0;")

#define LDSM_X4(R0, R1, R2, R3, ADDR)                                       \
    asm volatile("ldmatrix.sync.aligned.m8n8.x4.shared.b16 {%0,%1,%2,%3}, [%4];" \
                 : "=r"(R0), "=r"(R1), "=r"(R2), "=r"(R3) : "r"(ADDR));

// 3-stage smem: stage = A(128x36) + B
#define QK_SMEM3 (3 * (128 * 36 + 128 * 36) * 4)    // 110592
#define PV_SMEM3 (3 * (128 * 36 + 32 * 136) * 4)    // 107520
// A stage stride bytes = 128*36*4
#define A_STG 18432
#define A_TOT 55296

// =============================================================================
// Kernel 1: 3x3 conv as implicit-im2col tensor GEMM.
// Block = (n, band of 32 h-rows). M=24 (3 convs x 8 co, padded 32),
// K=72 (8ci x 3 x 3, padded 80), N=256 (32 h x 8 w). 8 warps, warp N=32.
// =============================================================================
#define CONV_SMEM (2720 * 4 + 32 * 84 * 4 + 80 * 264 * 4)   // 106112 bytes

__global__ void __launch_bounds__(256) conv3_mma(const float* __restrict__ x,
                                                 const float* __restrict__ wq,
                                                 const float* __restrict__ wk,
                                                 const float* __restrict__ wv) {
    extern __shared__ __align__(16) unsigned csm[];
    float (*s_in)[34][10] = (float(*)[34][10])csm;                 // 8*34*10 = 2720
    unsigned (*As)[84] = (unsigned(*)[84])(csm + 2720);            // 32 x 84
    unsigned (*Bs)[264] = (unsigned(*)[264])(csm + 2720 + 32 * 84);// 80 x 264

    const int n = blockIdx.x;        // n = b*512 + l
    const int band = blockIdx.y;
    const int b = n >> 9;
    const int l = n & 511;
    const int tid = threadIdx.x;
    const int lane = tid & 31;
    const int warp = tid >> 5;

    // A = stacked conv weights (tf32), zero-padded to 32x80
    for (int e = tid; e < 32 * 84; e += 256) {
        const int row = e / 84, k = e % 84;
        unsigned val = 0;
        if (row < 24 && k < 72) {
            const int q3 = row >> 3, co = row & 7;
            const float* ws = (q3 == 0) ? wq : (q3 == 1) ? wk : wv;
            val = f2tf(ws[co * 72 + k]);
        }
        As[row][k] = val;
    }

    // padded input tile
    for (int e = tid; e < 8 * 34 * 10; e += 256) {
        const int ci = e / 340;
        const int r = e % 340;
        const int yl = r / 10;
        const int xx = r % 10;
        const int gy = band * 32 + yl - 1;
        const int gx = xx - 1;
        float v = 0.f;
        if (gy >= 0 && gy < 256 && gx >= 0 && gx < 8)
            v = x[((((size_t)(b * 8 + ci) * 512 + l) * 256 + gy) * 8) + gx];
        s_in[ci][yl][xx] = v;
    }
    __syncthreads();

    // implicit im2col: Bs[k][col], col = y*8+x (local), k = ci*9 + dy*3 + dx
    for (int e = tid; e < 80 * 256; e += 256) {
        const int k = e >> 8, col = e & 255;
        unsigned val = 0;
        if (k < 72) {
            const int ci = k / 9, rem = k % 9, dy = rem / 3, dx = rem % 3;
            const int y = col >> 3, xx = col & 7;
            val = f2tf(s_in[ci][y + dy][xx + dx]);
        }
        Bs[k][col] = val;
    }
    __syncthreads();

    float C[2][4][4] = {};
    const int wn = warp;
#pragma unroll
    for (int ks = 0; ks < 10; ks++) {
        const int kk = ks * 8 + (lane & 3);
        unsigned a[2][4];
#pragma unroll
        for (int mi = 0; mi < 2; mi++) {
            const int r = mi * 16 + (lane >> 2);
            a[mi][0] = As[r][kk];     a[mi][1] = As[r + 8][kk];
            a[mi][2] = As[r][kk + 4]; a[mi][3] = As[r + 8][kk + 4];
        }
        unsigned bf[4][2];
#pragma unroll
        for (int ni = 0; ni < 4; ni++) {
            const int nn = wn * 32 + ni * 8 + (lane >> 2);
            bf[ni][0] = Bs[kk][nn];
            bf[ni][1] = Bs[kk + 4][nn];
        }
#pragma unroll
        for (int mi = 0; mi < 2; mi++)
#pragma unroll
            for (int ni = 0; ni < 4; ni++) mma8(C[mi][ni], a[mi], bf[ni]);
    }

#pragma unroll
    for (int mi = 0; mi < 2; mi++)
#pragma unroll
        for (int ni = 0; ni < 4; ni++)
#pragma unroll
            for (int e = 0; e < 4; e++) {
                const int row = mi * 16 + (lane >> 2) + (e >> 1) * 8;
                if (row < 24) {
                    const int col = wn * 32 + ni * 8 + (lane & 3) * 2 + (e & 1);
                    const int q3 = row >> 3, co = row & 7;
                    const int y = band * 32 + (col >> 3), xw = col & 7;
                    g_conv[(size_t)q3 * 16777216u + ((size_t)n * 8 + co) * 2048u +
                           (size_t)y * 8 + xw] = tfbits(C[mi][ni][e]);
                }
            }
}

// =============================================================================
// Kernel 1b: convert all weights to tf32 bits in g_wt
// =============================================================================
__global__ void wcvt_kernel(const float* __restrict__ wq, const float* __restrict__ wk,
                            const float* __restrict__ wv, const float* __restrict__ wo) {
    const int idx = blockIdx.x * 256 + threadIdx.x;
    const int t = idx >> 17;
    const float* src = (t == 0) ? wq : (t == 1) ? wk : (t == 2) ? wv : wo;
    const float4 v = ((const float4*)src)[idx & 131071];
    ((uint4*)g_wt)[idx] = make_uint4(f2tf(v.x), f2tf(v.y), f2tf(v.z), f2tf(v.w));
}

// =============================================================================
// GEMM geometry: block 128x128, k-step 32, 3-stage cp.async, ONE sync/iter.
// 8 warps (2 M x 4 N), warp tile 64x32, m16n8k8 tf32, ldmatrix fragment loads.
// =============================================================================

#define GEMM_THREAD_IDS                                                     \
    const int tid = threadIdx.x;                                            \
    const int lane = tid & 31;                                              \
    const int warp = tid >> 5;                                              \
    const int wm = warp >> 2, wn = warp & 3;                                \
    const int grp = lane >> 3, lrow = lane & 7;                             \
    const unsigned smem_u = (unsigned)__cvta_generic_to_shared(dynsmem);    \
    const unsigned a_loff =                                                 \
        ((wm * 64 + (grp & 1) * 8 + lrow) * 36 + (grp >> 1) * 4) * 4;

// A via ldmatrix, B via scalar LDS from k-major Bs[ST][32][136]
#define AB_COMPUTE(ST)                                                            \
    {                                                                             \
        const unsigned asb = smem_u + (unsigned)(ST) * A_STG;                     \
        _Pragma("unroll")                                                         \
        for (int ks = 0; ks < 4; ks++) {                                          \
            const int kk = ks * 8 + (lane & 3);                                   \
            unsigned a[4][4];                                                     \
            _Pragma("unroll")                                                     \
            for (int mi = 0; mi < 4; mi++)                                        \
                LDSM_X4(a[mi][0], a[mi][1], a[mi][2], a[mi][3],                   \
                        asb + a_loff + mi * 2304 + ks * 32)                       \
            unsigned bf[4][2];                                                    \
            _Pragma("unroll")                                                     \
            for (int ni = 0; ni < 4; ni++) {                                      \
                const int nn = wn * 32 + ni * 8 + (lane >> 2);                    \
                bf[ni][0] = Bs[ST][kk][nn];                                       \
                bf[ni][1] = Bs[ST][kk + 4][nn];                                   \
            }                                                                     \
            _Pragma("unroll")                                                     \
            for (int mi = 0; mi < 4; mi++)                                        \
                _Pragma("unroll")                                                 \
                for (int ni = 0; ni < 4; ni++) mma8(C[mi][ni], a[mi], bf[ni]);    \
        }                                                                         \
    }

// A and B both via ldmatrix (B stored n-major, [n][k], stride 36)
#define ABM_COMPUTE(ST)                                                           \
    {                                                                             \
        const unsigned asb = smem_u + (unsigned)(ST) * A_STG;                     \
        const unsigned bsb = smem_u + A_TOT + (unsigned)(ST) * A_STG;             \
        _Pragma("unroll")                                                         \
        for (int ks = 0; ks < 4; ks++) {                                          \
            unsigned a[4][4];                                                     \
            _Pragma("unroll")                                                     \
            for (int mi = 0; mi < 4; mi++)                                        \
                LDSM_X4(a[mi][0], a[mi][1], a[mi][2], a[mi][3],                   \
                        asb + a_loff + mi * 2304 + ks * 32)                       \
            unsigned bf[4][2];                                                    \
            _Pragma("unroll")                                                     \
            for (int np = 0; np < 2; np++)                                        \
                LDSM_X4(bf[np * 2][0], bf[np * 2][1], bf[np * 2 + 1][0],          \
                        bf[np * 2 + 1][1], bsb + b_loff + np * 2304 + ks * 32)    \
            _Pragma("unroll")                                                     \
            for (int mi = 0; mi < 4; mi++)                                        \
                _Pragma("unroll")                                                 \
                for (int ni = 0; ni < 4; ni++) mma8(C[mi][ni], a[mi], bf[ni]);    \
        }                                                                         \
    }

// pipeline driver: LOADM(stage, k0) must end with CP_COMMIT
#define PIPE_LOOP(KS, LOADM, COMPUTE)                     \
    LOADM(0, 0)                                           \
    LOADM(1, 32)                                          \
    _Pragma("unroll 1")                                   \
    for (int s = 0; s < (KS); s++) {                      \
        if (s + 1 < (KS)) { CP_WAIT1; } else { CP_WAIT0; }\
        __syncthreads();                                  \
        const int st = s % 3;                             \
        COMPUTE(st)                                       \
        if (s + 2 < (KS)) {                               \
            const int ld = (s + 2) % 3;                   \
            const int k0 = (s + 2) * 32;                  \
            LOADM(ld, k0)                                 \
        }                                                 \
    }

// =============================================================================
// Kernel 2: q/k/v linear + fused RoPE. A = g_wt[q3][c], B = g_conv.
// =============================================================================
__global__ void __launch_bounds__(256, 2) mlin_qkv_mma() {
    extern __shared__ __align__(16) unsigned dynsmem[];
    unsigned (*As)[128][36] = (unsigned(*)[128][36])dynsmem;
    unsigned (*Bs)[32][136] = (unsigned(*)[32][136])(dynsmem + 3 * 128 * 36);

    const int z = blockIdx.z;
    const int q3 = z >> 3;
    const int c = z & 7;
    const float* W = g_wt + (size_t)q3 * 524288 + (size_t)c * 65536;
    const float* Bsrc = g_conv + (size_t)q3 * 16777216u + (size_t)c * 2048;
    const int g0 = blockIdx.y * 128;
    const int colb = blockIdx.x * 16;    // n-index base (16 n per block)
    GEMM_THREAD_IDS

    float C[4][4][4] = {};

#define LOAD_QKV(ST, K0)                                                              \
    {                                                                                 \
        _Pragma("unroll")                                                             \
        for (int i = 0; i < 4; i++) {                                                 \
            const int idx = i * 256 + tid;                                            \
            const int row = idx >> 3, f4 = idx & 7;                                   \
            cp16(&As[ST][row][f4 * 4], W + (size_t)(g0 + row) * 256 + (K0) + f4 * 4); \
        }                                                                             \
        _Pragma("unroll")                                                             \
        for (int i = 0; i < 4; i++) {                                                 \
            const int idx = i * 256 + tid;                                            \
            const int w4 = idx & 1, nl = (idx >> 1) & 15, kb = idx >> 5;              \
            cp16(&Bs[ST][kb][nl * 8 + w4 * 4],                                        \
                 Bsrc + (size_t)(colb + nl) * 16384 + (size_t)((K0) + kb) * 8 + w4 * 4); \
        }                                                                             \
        CP_COMMIT;                                                                    \
    }

    PIPE_LOOP(8, LOAD_QKV, AB_COMPUTE)
#undef LOAD_QKV

    float* dst = (q3 == 0) ? g_q : (q3 == 1) ? g_k : g_v;
#pragma unroll
    for (int mi = 0; mi < 4; mi++) {
        const int gr = g0 + wm * 64 + mi * 16 + (lane >> 2);
#pragma unroll
        for (int ni = 0; ni < 4; ni++) {
            const int cc = colb * 8 + wn * 32 + ni * 8 + (lane & 3) * 2;
            const int n = cc >> 3, w0 = cc & 7;
            const int b = n >> 9, l = n & 511;
#pragma unroll
            for (int pr = 0; pr < 2; pr++) {
                const int g = gr + pr * 8;
                float v0 = C[mi][ni][pr * 2];
                float v1 = C[mi][ni][pr * 2 + 1];
                const int d0 = ((g & 31) << 3) | w0;
                if (q3 < 2 && d0 < 32) {       // fused RoPE on first 32 dims of q,k
                    const int ri = d0 >> 1;
                    const float inv = powf(10000.f, -(float)ri / 16.f);
                    const float f = (float)l * inv;
                    const float cs = cosf(f), sn = sinf(f);
                    const float r0 = v0 * cs - v1 * sn;
                    const float r1 = v1 * cs + v0 * sn;
                    v0 = r0; v1 = r1;
                }
                const int nh = g >> 5;
                const size_t base =
                    ((((size_t)(b * 8 + c) * 8 + nh) * 512 + l) * 256) + d0;
                dst[base]     = tfbits(v0);
                dst[base + 1] = tfbits(v1);
            }
        }
    }
}

// =============================================================================
// Kernel 4: S = Q K^T / 16 + prev. B tile = 128 K-rows, [row][k] layout (LDSM).
// =============================================================================
__global__ void __launch_bounds__(256, 2) qk_mma(const float* __restrict__ prev,
                                                 float* __restrict__ out_qk) {
    extern __shared__ __align__(16) unsigned dynsmem[];
    unsigned (*As)[128][36] = (unsigned(*)[128][36])dynsmem;
    unsigned (*Bs)[128][36] = (unsigned(*)[128][36])(dynsmem + 3 * 128 * 36);
    (void)Bs;

    const int head = blockIdx.z;
    const float* Q = g_q + (size_t)head * 131072;
    const float* K = g_k + (size_t)head * 131072;
    const int l0 = blockIdx.y * 128;
    const int m0 = blockIdx.x * 128;
    GEMM_THREAD_IDS
    const unsigned b_loff =
        ((wn * 32 + (grp >> 1) * 8 + lrow) * 36 + (grp & 1) * 4) * 4;

    float C[4][4][4] = {};

#define LOAD_QK(ST, K0)                                                               \
    {                                                                                 \
        _Pragma("unroll")                                                             \
        for (int i = 0; i < 4; i++) {                                                 \
            const int idx = i * 256 + tid;                                            \
            const int row = idx >> 3, f4 = idx & 7;                                   \
            cp16(&As[ST][row][f4 * 4], Q + (size_t)(l0 + row) * 256 + (K0) + f4 * 4); \
            cp16(&Bs[ST][row][f4 * 4], K + (size_t)(m0 + row) * 256 + (K0) + f4 * 4); \
        }                                                                             \
        CP_COMMIT;                                                                    \
    }

    PIPE_LOOP(8, LOAD_QK, ABM_COMPUTE)
#undef LOAD_QK

    const size_t hb = (size_t)head * 262144;
#pragma unroll
    for (int mi = 0; mi < 4; mi++) {
        const int r0 = l0 + wm * 64 + mi * 16 + (lane >> 2);
#pragma unroll
        for (int ni = 0; ni < 4; ni++) {
            const int c0 = m0 + wn * 32 + ni * 8 + (lane & 3) * 2;
            const size_t o0 = hb + (size_t)r0 * 512 + c0;
            const size_t o1 = hb + (size_t)(r0 + 8) * 512 + c0;
            out_qk[o0]     = C[mi][ni][0] * 0.0625f + prev[o0];
            out_qk[o0 + 1] = C[mi][ni][1] * 0.0625f + prev[o0 + 1];
            out_qk[o1]     = C[mi][ni][2] * 0.0625f + prev[o1];
            out_qk[o1 + 1] = C[mi][ni][3] * 0.0625f + prev[o1 + 1];
        }
    }
}

// =============================================================================
// Kernel 5: softmax -> normalized P (tf32 bits). One warp per 512-row.
// =============================================================================
__global__ void softmax_kernel(const float* __restrict__ qk) {
    const int row = blockIdx.x * 8 + (threadIdx.x >> 5);
    const int lane = threadIdx.x & 31;
    const float4* p4 = (const float4*)(qk + (size_t)row * 512);

    float4 v[4];
#pragma unroll
    for (int i = 0; i < 4; i++) v[i] = p4[lane + 32 * i];

    float m = -1e30f;
#pragma unroll
    for (int i = 0; i < 4; i++)
        m = fmaxf(m, fmaxf(fmaxf(v[i].x, v[i].y), fmaxf(v[i].z, v[i].w)));
#pragma unroll
    for (int s = 16; s > 0; s >>= 1) m = fmaxf(m, __shfl_xor_sync(0xFFFFFFFFu, m, s));

    const float L2E = 1.44269504088896f;
    float e[16];
    float sum = 0.f;
#pragma unroll
    for (int i = 0; i < 4; i++) {
        e[i * 4 + 0] = ex2((v[i].x - m) * L2E);
        e[i * 4 + 1] = ex2((v[i].y - m) * L2E);
        e[i * 4 + 2] = ex2((v[i].z - m) * L2E);
        e[i * 4 + 3] = ex2((v[i].w - m) * L2E);
        sum += e[i * 4 + 0] + e[i * 4 + 1] + e[i * 4 + 2] + e[i * 4 + 3];
    }
#pragma unroll
    for (int s = 16; s > 0; s >>= 1) sum += __shfl_xor_sync(0xFFFFFFFFu, sum, s);
    const float inv = 1.f / sum;

    uint4* q4 = (uint4*)(g_p + (size_t)row * 512);
#pragma unroll
    for (int i = 0; i < 4; i++) {
        q4[lane + 32 * i] = make_uint4(f2tf(e[i * 4 + 0] * inv), f2tf(e[i * 4 + 1] * inv),
                                       f2tf(e[i * 4 + 2] * inv), f2tf(e[i * 4 + 3] * inv));
    }
}

// =============================================================================
// Kernel 6: A = P @ V.
// =============================================================================
__global__ void __launch_bounds__(256, 2) pv_mma() {
    extern __shared__ __align__(16) unsigned dynsmem[];
    unsigned (*As)[128][36] = (unsigned(*)[128][36])dynsmem;
    unsigned (*Bs)[32][136] = (unsigned(*)[32][136])(dynsmem + 3 * 128 * 36);

    const int head = blockIdx.z;
    const int bc = head >> 3;
    const int nh = head & 7;
    const float* P = g_p + (size_t)head * 262144;
    const float* V = g_v + (size_t)head * 131072;
    const int l0 = blockIdx.y * 128;
    const int d0b = blockIdx.x * 128;
    GEMM_THREAD_IDS

    float C[4][4][4] = {};

#define LOAD_PV(ST, K0)                                                               \
    {                                                                                 \
        _Pragma("unroll")                                                             \
        for (int i = 0; i < 4; i++) {                                                 \
            const int idx = i * 256 + tid;                                            \
            const int row = idx >> 3, f4 = idx & 7;                                   \
            cp16(&As[ST][row][f4 * 4], P + (size_t)(l0 + row) * 512 + (K0) + f4 * 4); \
        }                                                                             \
        _Pragma("unroll")                                                             \
        for (int i = 0; i < 4; i++) {                                                 \
            const int idx = i * 256 + tid;                                            \
            const int kb = idx >> 5, n4 = idx & 31;                                   \
            cp16(&Bs[ST][kb][n4 * 4], V + (size_t)((K0) + kb) * 256 + d0b + n4 * 4);  \
        }                                                                             \
        CP_COMMIT;                                                                    \
    }

    PIPE_LOOP(16, LOAD_PV, AB_COMPUTE)
#undef LOAD_PV

#pragma unroll
    for (int mi = 0; mi < 4; mi++) {
        const int r0 = l0 + wm * 64 + mi * 16 + (lane >> 2);
#pragma unroll
        for (int ni = 0; ni < 4; ni++) {
            const int c0 = d0b + wn * 32 + ni * 8 + (lane & 3) * 2;
#pragma unroll
            for (int e = 0; e < 4; e++) {
                const int l = r0 + (e >> 1) * 8;
                const int d = c0 + (e & 1);
                const int hfeat = nh * 32 + (d >> 3);
                const int w = d & 7;
                g_a[((size_t)bc * 512 + l) * 2048 + (size_t)hfeat * 8 + w] =
                    tfbits(C[mi][ni][e]);
            }
        }
    }
}

// =============================================================================
// Kernel 7: output projection.
// =============================================================================
__global__ void __launch_bounds__(256, 2) mlin_out_mma(float* __restrict__ out) {
    extern __shared__ __align__(16) unsigned dynsmem[];
    unsigned (*As)[128][36] = (unsigned(*)[128][36])dynsmem;
    unsigned (*Bs)[32][136] = (unsigned(*)[32][136])(dynsmem + 3 * 128 * 36);

    const int c = blockIdx.z;
    const float* W = g_wt + 3u * 524288 + (size_t)c * 65536;
    const int g0 = blockIdx.y * 128;
    const int colb = blockIdx.x * 16;
    GEMM_THREAD_IDS

    float C[4][4][4] = {};

#define LOAD_OUT(ST, K0)                                                              \
    {                                                                                 \
        _Pragma("unroll")                                                             \
        for (int i = 0; i < 4; i++) {                                                 \
            const int idx = i * 256 + tid;                                            \
            const int row = idx >> 3, f4 = idx & 7;                                   \
            cp16(&As[ST][row][f4 * 4], W + (size_t)(g0 + row) * 256 + (K0) + f4 * 4); \
        }                                                                             \
        _Pragma("unroll")                                                             \
        for (int i = 0; i < 4; i++) {                                                 \
            const int idx = i * 256 + tid;                                            \
            const int w4 = idx & 1, nl = (idx >> 1) & 15, kb = idx >> 5;              \
            const int n = colb + nl;                                                  \
            const int b = n >> 9, l = n & 511;                                        \
            cp16(&Bs[ST][kb][nl * 8 + w4 * 4],                                        \
                 g_a + ((size_t)(b * 8 + c) * 512 + l) * 2048 +                       \
                     (size_t)((K0) + kb) * 8 + w4 * 4);                               \
        }                                                                             \
        CP_COMMIT;                                                                    \
    }

    PIPE_LOOP(8, LOAD_OUT, AB_COMPUTE)
#undef LOAD_OUT

#pragma unroll
    for (int mi = 0; mi < 4; mi++) {
        const int gr = g0 + wm * 64 + mi * 16 + (lane >> 2);
#pragma unroll
        for (int ni = 0; ni < 4; ni++) {
            const int cc = colb * 8 + wn * 32 + ni * 8 + (lane & 3) * 2;
#pragma unroll
            for (int e = 0; e < 4; e++) {
                const int g = gr + (e >> 1) * 8;
                const int cg = cc + (e & 1);
                const int n = cg >> 3, w = cg & 7;
                const int b = n >> 9, l = n & 511;
                out[(((size_t)(b * 8 + c) * 512 + l) * 256 + g) * 8 + w] = C[mi][ni][e];
            }
        }
    }
}

// =============================================================================
extern "C" void kernel_launch(void* const* d_in, const int* in_sizes, int n_in,
                              void* d_out, int out_size) {
    const float* x    = (const float*)d_in[0];
    const float* prev = (const float*)d_in[1];
    const float* cqw  = (const float*)d_in[2];
    const float* ckw  = (const float*)d_in[3];
    const float* cvw  = (const float*)d_in[4];
    const float* wq   = (const float*)d_in[5];
    const float* wk   = (const float*)d_in[6];
    const float* wv   = (const float*)d_in[7];
    const float* wo   = (const float*)d_in[8];
    float* out = (float*)d_out;
    float* out_qk = out + QK_OFF;

    static bool attr_done = false;
    if (!attr_done) {
        cudaFuncSetAttribute(conv3_mma, cudaFuncAttributeMaxDynamicSharedMemorySize, CONV_SMEM);
        cudaFuncSetAttribute(mlin_qkv_mma, cudaFuncAttributeMaxDynamicSharedMemorySize, PV_SMEM3);
        cudaFuncSetAttribute(qk_mma, cudaFuncAttributeMaxDynamicSharedMemorySize, QK_SMEM3);
        cudaFuncSetAttribute(pv_mma, cudaFuncAttributeMaxDynamicSharedMemorySize, PV_SMEM3);
        cudaFuncSetAttribute(mlin_out_mma, cudaFuncAttributeMaxDynamicSharedMemorySize, PV_SMEM3);
        attr_done = true;
    }

    conv3_mma<<<dim3(1024, 8), 256, CONV_SMEM>>>(x, cqw, ckw, cvw);
    wcvt_kernel<<<2048, 256>>>(wq, wk, wv, wo);
    mlin_qkv_mma<<<dim3(64, 2, 24), 256, PV_SMEM3>>>();
    qk_mma<<<dim3(4, 4, 128), 256, QK_SMEM3>>>(prev, out_qk);
    softmax_kernel<<<8192, 256>>>(out_qk);
    pv_mma<<<dim3(2, 4, 128), 256, PV_SMEM3>>>();
    mlin_out_mma<<<dim3(64, 2, 8), 256, PV_SMEM3>>>(out);
}

// round 15
// speedup vs baseline: 1.1086x; 1.1086x over previous
#include <cuda_runtime.h>
#include <math.h>

// x: (2,8,512,256,8), prev_qk: (2,8,8,512,512), conv w: (8,8,3,3), w*: (8,256,256)
// out = out(2,8,512,256,8) ++ qk(2,8,8,512,512)
#define QK_OFF 16777216ull

// ---------------- scratch (tf32 bit patterns stored as float) ----------------
__device__ float g_conv[3u * 1024u * 8u * 256u * 8u];   // [qkv][n][c][h][w] (tf32)
__device__ float g_q[128u * 512u * 256u];               // [head][l][d] (tf32)
__device__ float g_k[128u * 512u * 256u];
__device__ float g_v[128u * 512u * 256u];
__device__ float g_p[128u * 512u * 512u];               // normalized probs (tf32)
__device__ float g_a[16u * 512u * 2048u];               // [bc][l][h][w] (tf32)
__device__ float g_wt[4u * 8u * 256u * 256u];           // weights (tf32): wq,wk,wv,wo

// ---------------- helpers ----------------
__device__ __forceinline__ unsigned f2tf(float x) {
    unsigned u;
    asm("cvt.rna.tf32.f32 %0, %1;" : "=r"(u) : "f"(x));
    return u;
}
__device__ __forceinline__ float tfbits(float x) { return __uint_as_float(f2tf(x)); }
__device__ __forceinline__ void mma8(float c[4], const unsigned a[4], const unsigned b[2]) {
    asm volatile(
        "mma.sync.aligned.m16n8k8.row.col.f32.tf32.tf32.f32 "
        "{%0,%1,%2,%3},{%4,%5,%6,%7},{%8,%9},{%0,%1,%2,%3};"
        : "+f"(c[0]), "+f"(c[1]), "+f"(c[2]), "+f"(c[3])
        : "r"(a[0]), "r"(a[1]), "r"(a[2]), "r"(a[3]), "r"(b[0]), "r"(b[1]));
}
__device__ __forceinline__ float ex2(float x) {
    float r;
    asm("ex2.approx.f32 %0, %1;" : "=f"(r) : "f"(x));
    return r;
}
__device__ __forceinline__ void cp16(void* dst, const void* src) {
    unsigned d = (unsigned)__cvta_generic_to_shared(dst);
    asm volatile("cp.async.cg.shared.global [%0], [%1], 16;" :: "r"(d), "l"(src));
}
#define CP_COMMIT asm volatile("cp.async.commit_group;")
#define CP_WAIT1 asm volatile("cp.async.wait_group 1;")
#define CP_WAIT0 asm volatile("cp.async.wait_group 0;")

#define LDSM_X4(R0, R1, R2, R3, ADDR)                                       \
    asm volatile("ldmatrix.sync.aligned.m8n8.x4.shared.b16 {%0,%1,%2,%3}, [%4];" \
                 : "=r"(R0), "=r"(R1), "=r"(R2), "=r"(R3) : "r"(ADDR));

// 3-stage smem: stage = A(128x36) + B
#define QK_SMEM3 (3 * (128 * 36 + 128 * 36) * 4)    // 110592
#define PV_SMEM3 (3 * (128 * 36 + 32 * 136) * 4)    // 107520
// A stage stride bytes = 128*36*4
#define A_STG 18432
#define A_TOT 55296

// =============================================================================
// Kernel 1: 3x3 conv (FFMA; bit-exact fp32 then tf32-quantize at store)
// =============================================================================
__global__ void conv3_kernel(const float* __restrict__ x,
                             const float* __restrict__ wq,
                             const float* __restrict__ wk,
                             const float* __restrict__ wv) {
    __shared__ float s_in[8][34][10];
    __shared__ float s_w[3][8][8][9];

    const int n = blockIdx.x;
    const int band = blockIdx.y;
    const int b = n >> 9;
    const int l = n & 511;
    const int tid = threadIdx.x;

    for (int e = tid; e < 3 * 576; e += 256) {
        const int q3 = e / 576;
        const int r = e % 576;
        const float* ws = (q3 == 0) ? wq : (q3 == 1) ? wk : wv;
        ((float*)s_w)[e] = ws[r];
    }
    for (int e = tid; e < 8 * 34 * 10; e += 256) {
        const int ci = e / 340;
        const int r = e % 340;
        const int yl = r / 10;
        const int xx = r % 10;
        const int gy = band * 32 + yl - 1;
        const int gx = xx - 1;
        float v = 0.f;
        if (gy >= 0 && gy < 256 && gx >= 0 && gx < 8)
            v = x[((((size_t)(b * 8 + ci) * 512 + l) * 256 + gy) * 8) + gx];
        s_in[ci][yl][xx] = v;
    }
    __syncthreads();

    const int j = tid & 7;
    const int il = tid >> 3;

    float acc[24];
#pragma unroll
    for (int i = 0; i < 24; i++) acc[i] = 0.f;

#pragma unroll
    for (int ci = 0; ci < 8; ci++) {
        float v[9];
#pragma unroll
        for (int di = 0; di < 3; di++)
#pragma unroll
            for (int dj = 0; dj < 3; dj++)
                v[di * 3 + dj] = s_in[ci][il + di][j + dj];
#pragma unroll
        for (int q3 = 0; q3 < 3; q3++)
#pragma unroll
            for (int co = 0; co < 8; co++) {
                const float* wp = s_w[q3][co][ci];
                float a = acc[q3 * 8 + co];
#pragma unroll
                for (int t = 0; t < 9; t++) a = fmaf(v[t], wp[t], a);
                acc[q3 * 8 + co] = a;
            }
    }

    const int y = band * 32 + il;
#pragma unroll
    for (int q3 = 0; q3 < 3; q3++)
#pragma unroll
        for (int co = 0; co < 8; co++)
            g_conv[(size_t)q3 * 16777216u + ((size_t)n * 8 + co) * 2048u + (size_t)y * 8 + j] =
                tfbits(acc[q3 * 8 + co]);
}

// =============================================================================
// Kernel 1b: convert all weights to tf32 bits in g_wt
// =============================================================================
__global__ void wcvt_kernel(const float* __restrict__ wq, const float* __restrict__ wk,
                            const float* __restrict__ wv, const float* __restrict__ wo) {
    const int idx = blockIdx.x * 256 + threadIdx.x;
    const int t = idx >> 17;
    const float* src = (t == 0) ? wq : (t == 1) ? wk : (t == 2) ? wv : wo;
    const float4 v = ((const float4*)src)[idx & 131071];
    ((uint4*)g_wt)[idx] = make_uint4(f2tf(v.x), f2tf(v.y), f2tf(v.z), f2tf(v.w));
}

// =============================================================================
// GEMM geometry: block 128x128, k-step 32, 3-stage cp.async, ONE sync/iter.
// 4 warps (2 M x 2 N), warp tile 64x64, m16n8k8 tf32, ldmatrix A (and B when
// n-major). 128 threads/CTA, 2 CTAs/SM.
// =============================================================================

#define GEMM_THREAD_IDS                                                     \
    const int tid = threadIdx.x;                                            \
    const int lane = tid & 31;                                              \
    const int warp = tid >> 5;                                              \
    const int wm = warp >> 1, wn = warp & 1;                                \
    const int grp = lane >> 3, lrow = lane & 7;                             \
    const unsigned smem_u = (unsigned)__cvta_generic_to_shared(dynsmem);    \
    const unsigned a_loff =                                                 \
        ((wm * 64 + (grp & 1) * 8 + lrow) * 36 + (grp >> 1) * 4) * 4;

// A via ldmatrix, B via scalar LDS from k-major Bs[ST][32][136]
#define AB_COMPUTE(ST)                                                            \
    {                                                                             \
        const unsigned asb = smem_u + (unsigned)(ST) * A_STG;                     \
        _Pragma("unroll")                                                         \
        for (int ks = 0; ks < 4; ks++) {                                          \
            const int kk = ks * 8 + (lane & 3);                                   \
            unsigned a[4][4];                                                     \
            _Pragma("unroll")                                                     \
            for (int mi = 0; mi < 4; mi++)                                        \
                LDSM_X4(a[mi][0], a[mi][1], a[mi][2], a[mi][3],                   \
                        asb + a_loff + mi * 2304 + ks * 32)                       \
            unsigned bf[8][2];                                                    \
            _Pragma("unroll")                                                     \
            for (int ni = 0; ni < 8; ni++) {                                      \
                const int nn = wn * 64 + ni * 8 + (lane >> 2);                    \
                bf[ni][0] = Bs[ST][kk][nn];                                       \
                bf[ni][1] = Bs[ST][kk + 4][nn];                                   \
            }                                                                     \
            _Pragma("unroll")                                                     \
            for (int mi = 0; mi < 4; mi++)                                        \
                _Pragma("unroll")                                                 \
                for (int ni = 0; ni < 8; ni++) mma8(C[mi][ni], a[mi], bf[ni]);    \
        }                                                                         \
    }

// A and B both via ldmatrix (B stored n-major, [n][k], stride 36)
#define ABM_COMPUTE(ST)                                                           \
    {                                                                             \
        const unsigned asb = smem_u + (unsigned)(ST) * A_STG;                     \
        const unsigned bsb = smem_u + A_TOT + (unsigned)(ST) * A_STG;             \
        _Pragma("unroll")                                                         \
        for (int ks = 0; ks < 4; ks++) {                                          \
            unsigned a[4][4];                                                     \
            _Pragma("unroll")                                                     \
            for (int mi = 0; mi < 4; mi++)                                        \
                LDSM_X4(a[mi][0], a[mi][1], a[mi][2], a[mi][3],                   \
                        asb + a_loff + mi * 2304 + ks * 32)                       \
            unsigned bf[8][2];                                                    \
            _Pragma("unroll")                                                     \
            for (int np = 0; np < 4; np++)                                        \
                LDSM_X4(bf[np * 2][0], bf[np * 2][1], bf[np * 2 + 1][0],          \
                        bf[np * 2 + 1][1], bsb + b_loff + np * 2304 + ks * 32)    \
            _Pragma("unroll")                                                     \
            for (int mi = 0; mi < 4; mi++)                                        \
                _Pragma("unroll")                                                 \
                for (int ni = 0; ni < 8; ni++) mma8(C[mi][ni], a[mi], bf[ni]);    \
        }                                                                         \
    }

// pipeline driver: LOADM(stage, k0) must end with CP_COMMIT
#define PIPE_LOOP(KS, LOADM, COMPUTE)                     \
    LOADM(0, 0)                                           \
    LOADM(1, 32)                                          \
    _Pragma("unroll 1")                                   \
    for (int s = 0; s < (KS); s++) {                      \
        if (s + 1 < (KS)) { CP_WAIT1; } else { CP_WAIT0; }\
        __syncthreads();                                  \
        const int st = s % 3;                             \
        COMPUTE(st)                                       \
        if (s + 2 < (KS)) {                               \
            const int ld = (s + 2) % 3;                   \
            const int k0 = (s + 2) * 32;                  \
            LOADM(ld, k0)                                 \
        }                                                 \
    }

// =============================================================================
// Kernel 2: q/k/v linear + fused RoPE. A = g_wt[q3][c], B = g_conv.
// =============================================================================
__global__ void __launch_bounds__(128) mlin_qkv_mma() {
    extern __shared__ __align__(16) unsigned dynsmem[];
    unsigned (*As)[128][36] = (unsigned(*)[128][36])dynsmem;
    unsigned (*Bs)[32][136] = (unsigned(*)[32][136])(dynsmem + 3 * 128 * 36);

    const int z = blockIdx.z;
    const int q3 = z >> 3;
    const int c = z & 7;
    const float* W = g_wt + (size_t)q3 * 524288 + (size_t)c * 65536;
    const float* Bsrc = g_conv + (size_t)q3 * 16777216u + (size_t)c * 2048;
    const int g0 = blockIdx.y * 128;
    const int colb = blockIdx.x * 16;    // n-index base (16 n per block)
    GEMM_THREAD_IDS

    float C[4][8][4] = {};

#define LOAD_QKV(ST, K0)                                                              \
    {                                                                                 \
        _Pragma("unroll")                                                             \
        for (int i = 0; i < 8; i++) {                                                 \
            const int idx = i * 128 + tid;                                            \
            const int row = idx >> 3, f4 = idx & 7;                                   \
            cp16(&As[ST][row][f4 * 4], W + (size_t)(g0 + row) * 256 + (K0) + f4 * 4); \
        }                                                                             \
        _Pragma("unroll")                                                             \
        for (int i = 0; i < 8; i++) {                                                 \
            const int idx = i * 128 + tid;                                            \
            const int w4 = idx & 1, nl = (idx >> 1) & 15, kb = idx >> 5;              \
            cp16(&Bs[ST][kb][nl * 8 + w4 * 4],                                        \
                 Bsrc + (size_t)(colb + nl) * 16384 + (size_t)((K0) + kb) * 8 + w4 * 4); \
        }                                                                             \
        CP_COMMIT;                                                                    \
    }

    PIPE_LOOP(8, LOAD_QKV, AB_COMPUTE)
#undef LOAD_QKV

    float* dst = (q3 == 0) ? g_q : (q3 == 1) ? g_k : g_v;
#pragma unroll
    for (int mi = 0; mi < 4; mi++) {
        const int gr = g0 + wm * 64 + mi * 16 + (lane >> 2);
#pragma unroll
        for (int ni = 0; ni < 8; ni++) {
            const int cc = colb * 8 + wn * 64 + ni * 8 + (lane & 3) * 2;
            const int n = cc >> 3, w0 = cc & 7;
            const int b = n >> 9, l = n & 511;
#pragma unroll
            for (int pr = 0; pr < 2; pr++) {
                const int g = gr + pr * 8;
                float v0 = C[mi][ni][pr * 2];
                float v1 = C[mi][ni][pr * 2 + 1];
                const int d0 = ((g & 31) << 3) | w0;
                if (q3 < 2 && d0 < 32) {       // fused RoPE on first 32 dims of q,k
                    const int ri = d0 >> 1;
                    const float inv = powf(10000.f, -(float)ri / 16.f);
                    const float f = (float)l * inv;
                    const float cs = cosf(f), sn = sinf(f);
                    const float r0 = v0 * cs - v1 * sn;
                    const float r1 = v1 * cs + v0 * sn;
                    v0 = r0; v1 = r1;
                }
                const int nh = g >> 5;
                const size_t base =
                    ((((size_t)(b * 8 + c) * 8 + nh) * 512 + l) * 256) + d0;
                dst[base]     = tfbits(v0);
                dst[base + 1] = tfbits(v1);
            }
        }
    }
}

// =============================================================================
// Kernel 4: S = Q K^T / 16 + prev. B tile = 128 K-rows, [row][k] layout (LDSM).
// =============================================================================
__global__ void __launch_bounds__(128) qk_mma(const float* __restrict__ prev,
                                              float* __restrict__ out_qk) {
    extern __shared__ __align__(16) unsigned dynsmem[];
    unsigned (*As)[128][36] = (unsigned(*)[128][36])dynsmem;
    unsigned (*Bs)[128][36] = (unsigned(*)[128][36])(dynsmem + 3 * 128 * 36);
    (void)Bs;

    const int head = blockIdx.z;
    const float* Q = g_q + (size_t)head * 131072;
    const float* K = g_k + (size_t)head * 131072;
    const int l0 = blockIdx.y * 128;
    const int m0 = blockIdx.x * 128;
    GEMM_THREAD_IDS
    const unsigned b_loff =
        ((wn * 64 + (grp >> 1) * 8 + lrow) * 36 + (grp & 1) * 4) * 4;

    float C[4][8][4] = {};

#define LOAD_QK(ST, K0)                                                               \
    {                                                                                 \
        _Pragma("unroll")                                                             \
        for (int i = 0; i < 8; i++) {                                                 \
            const int idx = i * 128 + tid;                                            \
            const int row = idx >> 3, f4 = idx & 7;                                   \
            cp16(&As[ST][row][f4 * 4], Q + (size_t)(l0 + row) * 256 + (K0) + f4 * 4); \
            cp16(&Bs[ST][row][f4 * 4], K + (size_t)(m0 + row) * 256 + (K0) + f4 * 4); \
        }                                                                             \
        CP_COMMIT;                                                                    \
    }

    PIPE_LOOP(8, LOAD_QK, ABM_COMPUTE)
#undef LOAD_QK

    const size_t hb = (size_t)head * 262144;
#pragma unroll
    for (int mi = 0; mi < 4; mi++) {
        const int r0 = l0 + wm * 64 + mi * 16 + (lane >> 2);
#pragma unroll
        for (int ni = 0; ni < 8; ni++) {
            const int c0 = m0 + wn * 64 + ni * 8 + (lane & 3) * 2;
            const size_t o0 = hb + (size_t)r0 * 512 + c0;
            const size_t o1 = hb + (size_t)(r0 + 8) * 512 + c0;
            out_qk[o0]     = C[mi][ni][0] * 0.0625f + prev[o0];
            out_qk[o0 + 1] = C[mi][ni][1] * 0.0625f + prev[o0 + 1];
            out_qk[o1]     = C[mi][ni][2] * 0.0625f + prev[o1];
            out_qk[o1 + 1] = C[mi][ni][3] * 0.0625f + prev[o1 + 1];
        }
    }
}

// =============================================================================
// Kernel 5: softmax -> normalized P (tf32 bits). One warp per 512-row.
// =============================================================================
__global__ void softmax_kernel(const float* __restrict__ qk) {
    const int row = blockIdx.x * 8 + (threadIdx.x >> 5);
    const int lane = threadIdx.x & 31;
    const float4* p4 = (const float4*)(qk + (size_t)row * 512);

    float4 v[4];
#pragma unroll
    for (int i = 0; i < 4; i++) v[i] = p4[lane + 32 * i];

    float m = -1e30f;
#pragma unroll
    for (int i = 0; i < 4; i++)
        m = fmaxf(m, fmaxf(fmaxf(v[i].x, v[i].y), fmaxf(v[i].z, v[i].w)));
#pragma unroll
    for (int s = 16; s > 0; s >>= 1) m = fmaxf(m, __shfl_xor_sync(0xFFFFFFFFu, m, s));

    const float L2E = 1.44269504088896f;
    float e[16];
    float sum = 0.f;
#pragma unroll
    for (int i = 0; i < 4; i++) {
        e[i * 4 + 0] = ex2((v[i].x - m) * L2E);
        e[i * 4 + 1] = ex2((v[i].y - m) * L2E);
        e[i * 4 + 2] = ex2((v[i].z - m) * L2E);
        e[i * 4 + 3] = ex2((v[i].w - m) * L2E);
        sum += e[i * 4 + 0] + e[i * 4 + 1] + e[i * 4 + 2] + e[i * 4 + 3];
    }
#pragma unroll
    for (int s = 16; s > 0; s >>= 1) sum += __shfl_xor_sync(0xFFFFFFFFu, sum, s);
    const float inv = 1.f / sum;

    uint4* q4 = (uint4*)(g_p + (size_t)row * 512);
#pragma unroll
    for (int i = 0; i < 4; i++) {
        q4[lane + 32 * i] = make_uint4(f2tf(e[i * 4 + 0] * inv), f2tf(e[i * 4 + 1] * inv),
                                       f2tf(e[i * 4 + 2] * inv), f2tf(e[i * 4 + 3] * inv));
    }
}

// =============================================================================
// Kernel 6: A = P @ V.
// =============================================================================
__global__ void __launch_bounds__(128) pv_mma() {
    extern __shared__ __align__(16) unsigned dynsmem[];
    unsigned (*As)[128][36] = (unsigned(*)[128][36])dynsmem;
    unsigned (*Bs)[32][136] = (unsigned(*)[32][136])(dynsmem + 3 * 128 * 36);

    const int head = blockIdx.z;
    const int bc = head >> 3;
    const int nh = head & 7;
    const float* P = g_p + (size_t)head * 262144;
    const float* V = g_v + (size_t)head * 131072;
    const int l0 = blockIdx.y * 128;
    const int d0b = blockIdx.x * 128;
    GEMM_THREAD_IDS

    float C[4][8][4] = {};

#define LOAD_PV(ST, K0)                                                               \
    {                                                                                 \
        _Pragma("unroll")                                                             \
        for (int i = 0; i < 8; i++) {                                                 \
            const int idx = i * 128 + tid;                                            \
            const int row = idx >> 3, f4 = idx & 7;                                   \
            cp16(&As[ST][row][f4 * 4], P + (size_t)(l0 + row) * 512 + (K0) + f4 * 4); \
        }                                                                             \
        _Pragma("unroll")                                                             \
        for (int i = 0; i < 8; i++) {                                                 \
            const int idx = i * 128 + tid;                                            \
            const int kb = idx >> 5, n4 = idx & 31;                                   \
            cp16(&Bs[ST][kb][n4 * 4], V + (size_t)((K0) + kb) * 256 + d0b + n4 * 4);  \
        }                                                                             \
        CP_COMMIT;                                                                    \
    }

    PIPE_LOOP(16, LOAD_PV, AB_COMPUTE)
#undef LOAD_PV

#pragma unroll
    for (int mi = 0; mi < 4; mi++) {
        const int r0 = l0 + wm * 64 + mi * 16 + (lane >> 2);
#pragma unroll
        for (int ni = 0; ni < 8; ni++) {
            const int c0 = d0b + wn * 64 + ni * 8 + (lane & 3) * 2;
#pragma unroll
            for (int e = 0; e < 4; e++) {
                const int l = r0 + (e >> 1) * 8;
                const int d = c0 + (e & 1);
                const int hfeat = nh * 32 + (d >> 3);
                const int w = d & 7;
                g_a[((size_t)bc * 512 + l) * 2048 + (size_t)hfeat * 8 + w] =
                    tfbits(C[mi][ni][e]);
            }
        }
    }
}

// =============================================================================
// Kernel 7: output projection.
// =============================================================================
__global__ void __launch_bounds__(128) mlin_out_mma(float* __restrict__ out) {
    extern __shared__ __align__(16) unsigned dynsmem[];
    unsigned (*As)[128][36] = (unsigned(*)[128][36])dynsmem;
    unsigned (*Bs)[32][136] = (unsigned(*)[32][136])(dynsmem + 3 * 128 * 36);

    const int c = blockIdx.z;
    const float* W = g_wt + 3u * 524288 + (size_t)c * 65536;
    const int g0 = blockIdx.y * 128;
    const int colb = blockIdx.x * 16;
    GEMM_THREAD_IDS

    float C[4][8][4] = {};

#define LOAD_OUT(ST, K0)                                                              \
    {                                                                                 \
        _Pragma("unroll")                                                             \
        for (int i = 0; i < 8; i++) {                                                 \
            const int idx = i * 128 + tid;                                            \
            const int row = idx >> 3, f4 = idx & 7;                                   \
            cp16(&As[ST][row][f4 * 4], W + (size_t)(g0 + row) * 256 + (K0) + f4 * 4); \
        }                                                                             \
        _Pragma("unroll")                                                             \
        for (int i = 0; i < 8; i++) {                                                 \
            const int idx = i * 128 + tid;                                            \
            const int w4 = idx & 1, nl = (idx >> 1) & 15, kb = idx >> 5;              \
            const int n = colb + nl;                                                  \
            const int b = n >> 9, l = n & 511;                                        \
            cp16(&Bs[ST][kb][nl * 8 + w4 * 4],                                        \
                 g_a + ((size_t)(b * 8 + c) * 512 + l) * 2048 +                       \
                     (size_t)((K0) + kb) * 8 + w4 * 4);                               \
        }                                                                             \
        CP_COMMIT;                                                                    \
    }

    PIPE_LOOP(8, LOAD_OUT, AB_COMPUTE)
#undef LOAD_OUT

#pragma unroll
    for (int mi = 0; mi < 4; mi++) {
        const int gr = g0 + wm * 64 + mi * 16 + (lane >> 2);
#pragma unroll
        for (int ni = 0; ni < 8; ni++) {
            const int cc = colb * 8 + wn * 64 + ni * 8 + (lane & 3) * 2;
#pragma unroll
            for (int e = 0; e < 4; e++) {
                const int g = gr + (e >> 1) * 8;
                const int cg = cc + (e & 1);
                const int n = cg >> 3, w = cg & 7;
                const int b = n >> 9, l = n & 511;
                out[(((size_t)(b * 8 + c) * 512 + l) * 256 + g) * 8 + w] = C[mi][ni][e];
            }
        }
    }
}

// =============================================================================
extern "C" void kernel_launch(void* const* d_in, const int* in_sizes, int n_in,
                              void* d_out, int out_size) {
    const float* x    = (const float*)d_in[0];
    const float* prev = (const float*)d_in[1];
    const float* cqw  = (const float*)d_in[2];
    const float* ckw  = (const float*)d_in[3];
    const float* cvw  = (const float*)d_in[4];
    const float* wq   = (const float*)d_in[5];
    const float* wk   = (const float*)d_in[6];
    const float* wv   = (const float*)d_in[7];
    const float* wo   = (const float*)d_in[8];
    float* out = (float*)d_out;
    float* out_qk = out + QK_OFF;

    static bool attr_done = false;
    if (!attr_done) {
        cudaFuncSetAttribute(mlin_qkv_mma, cudaFuncAttributeMaxDynamicSharedMemorySize, PV_SMEM3);
        cudaFuncSetAttribute(qk_mma, cudaFuncAttributeMaxDynamicSharedMemorySize, QK_SMEM3);
        cudaFuncSetAttribute(pv_mma, cudaFuncAttributeMaxDynamicSharedMemorySize, PV_SMEM3);
        cudaFuncSetAttribute(mlin_out_mma, cudaFuncAttributeMaxDynamicSharedMemorySize, PV_SMEM3);
        attr_done = true;
    }

    conv3_kernel<<<dim3(1024, 8), 256>>>(x, cqw, ckw, cvw);
    wcvt_kernel<<<2048, 256>>>(wq, wk, wv, wo);
    mlin_qkv_mma<<<dim3(64, 2, 24), 128, PV_SMEM3>>>();
    qk_mma<<<dim3(4, 4, 128), 128, QK_SMEM3>>>(prev, out_qk);
    softmax_kernel<<<8192, 256>>>(out_qk);
    pv_mma<<<dim3(2, 4, 128), 128, PV_SMEM3>>>();
    mlin_out_mma<<<dim3(64, 2, 8), 128, PV_SMEM3>>>(out);
}